// round 1
// baseline (speedup 1.0000x reference)
#include <cuda_runtime.h>
#include <cuda_fp16.h>
#include <cstdint>

// Problem constants
#define N_ATOMS 100000
#define N_EDGES 1000000
#define HID 64
#define OUTD 128

// Scratch (device globals: allocation-free rule)
__device__ float  g_x[N_ATOMS * HID];      // node features
__device__ float  g_lin[N_ATOMS * HID];    // x @ W_lin + b_lin (fp32: feeds messages + self-update)
__device__ float  g_agg[N_ATOMS * HID];    // scatter-add accumulator
__device__ __half g_gtop[N_ATOMS * HID];   // x @ Wg_top + b_gate (gate pre-act, fp16 ok)
__device__ __half g_gbot[N_ATOMS * HID];   // x @ Wg_bot
__device__ float  g_pooled[HID];

// ---------------------------------------------------------------------------
// 1. Embedding lookup + zero agg + zero pooled
// ---------------------------------------------------------------------------
__global__ void __launch_bounds__(256) embed_kernel(const int* __restrict__ an,
                                                    const float* __restrict__ emb) {
    int i = blockIdx.x * 256 + threadIdx.x;
    if (i < N_ATOMS * HID) {
        int v = i >> 6;
        g_x[i] = emb[an[v] * HID + (i & 63)];
        g_agg[i] = 0.0f;
    }
    if (i < HID) g_pooled[i] = 0.0f;
}

// ---------------------------------------------------------------------------
// 2. Per-node projection: [64 nodes/block] x (64 -> 192) GEMM
//    cols 0..63   -> gtop (fp16, + b_gate folded in)
//    cols 64..127 -> gbot (fp16)
//    cols 128..191-> lin  (fp32, + b_lin)
// smem: xsT[64][68] transposed x-tile + ws[64][192] weights
// ---------------------------------------------------------------------------
#define XS_STRIDE 68
#define PROJ_SMEM ((64 * XS_STRIDE + 64 * 192) * 4)

__global__ void __launch_bounds__(256) proj_kernel(const float* __restrict__ Wg,
                                                   const float* __restrict__ bg,
                                                   const float* __restrict__ Wl,
                                                   const float* __restrict__ bl) {
    extern __shared__ float sm[];
    float* xsT = sm;                    // [64][XS_STRIDE]
    float* ws  = sm + 64 * XS_STRIDE;   // [64][192]

    const int tid = threadIdx.x;
    const int node0 = blockIdx.x * 64;

    // load x tile transposed: xsT[k][n] = x[node0+n][k]
    for (int i = tid; i < 64 * 64; i += 256) {
        int k = i & 63, n = i >> 6;
        int node = node0 + n;
        xsT[k * XS_STRIDE + n] = (node < N_ATOMS) ? g_x[node * HID + k] : 0.0f;
    }
    // load fused weights ws[k][c]
    for (int i = tid; i < 64 * 192; i += 256) {
        int k = i / 192, c = i - k * 192;
        float w;
        if (c < 64)        w = Wg[k * 64 + c];            // Wg_top
        else if (c < 128)  w = Wg[(64 + k) * 64 + (c - 64)]; // Wg_bot
        else               w = Wl[k * 64 + (c - 128)];    // W_lin
        ws[i] = w;
    }
    __syncthreads();

    const int ng = tid & 7;       // node group: 8 groups of 8 nodes
    const int cg = tid >> 3;      // col group : 32 groups of 6 cols
    const int nb = ng * 8;
    const int cb = cg * 6;

    float acc[8][6];
    #pragma unroll
    for (int n = 0; n < 8; n++)
        #pragma unroll
        for (int j = 0; j < 6; j++) acc[n][j] = 0.0f;

    #pragma unroll 8
    for (int k = 0; k < 64; k++) {
        const float* xr = &xsT[k * XS_STRIDE + nb];
        float4 a0 = *reinterpret_cast<const float4*>(xr);
        float4 a1 = *reinterpret_cast<const float4*>(xr + 4);
        float a[8] = {a0.x, a0.y, a0.z, a0.w, a1.x, a1.y, a1.z, a1.w};
        float b[6];
        #pragma unroll
        for (int j = 0; j < 6; j++) b[j] = ws[k * 192 + cb + j];
        #pragma unroll
        for (int n = 0; n < 8; n++)
            #pragma unroll
            for (int j = 0; j < 6; j++) acc[n][j] += a[n] * b[j];
    }

    // epilogue
    for (int n = 0; n < 8; n++) {
        int node = node0 + nb + n;
        if (node >= N_ATOMS) break;
        #pragma unroll
        for (int j = 0; j < 6; j++) {
            int c = cb + j;
            if (c < 64) {
                g_gtop[node * HID + c] = __float2half(acc[n][j] + bg[c]);
            } else if (c < 128) {
                g_gbot[node * HID + (c - 64)] = __float2half(acc[n][j]);
            } else {
                g_lin[node * HID + (c - 128)] = acc[n][j] + bl[c - 128];
            }
        }
    }
}

// ---------------------------------------------------------------------------
// 3. Edge kernel: 8 lanes/edge, each lane handles 8 of the 64 channels.
//    agg[row] += sigmoid(gtop[row] + gbot[col]) * lin[col]
// ---------------------------------------------------------------------------
__global__ void __launch_bounds__(256) edge_kernel(const int* __restrict__ ei) {
    int t = blockIdx.x * 256 + threadIdx.x;
    int e = t >> 3;
    if (e >= N_EDGES) return;
    int sub = (t & 7) * 8;

    int r = __ldg(&ei[e]);
    int c = __ldg(&ei[N_EDGES + e]);

    uint4 gt = *reinterpret_cast<const uint4*>(g_gtop + (size_t)r * HID + sub);
    uint4 gb = *reinterpret_cast<const uint4*>(g_gbot + (size_t)c * HID + sub);
    float4 l0 = *reinterpret_cast<const float4*>(g_lin + (size_t)c * HID + sub);
    float4 l1 = *reinterpret_cast<const float4*>(g_lin + (size_t)c * HID + sub + 4);

    const __half2* ht = reinterpret_cast<const __half2*>(&gt);
    const __half2* hb = reinterpret_cast<const __half2*>(&gb);

    float pre[8];
    #pragma unroll
    for (int j = 0; j < 4; j++) {
        float2 fa = __half22float2(ht[j]);
        float2 fb = __half22float2(hb[j]);
        pre[2 * j]     = fa.x + fb.x;
        pre[2 * j + 1] = fa.y + fb.y;
    }
    float lv[8] = {l0.x, l0.y, l0.z, l0.w, l1.x, l1.y, l1.z, l1.w};
    float m[8];
    #pragma unroll
    for (int j = 0; j < 8; j++) {
        float gte = __fdividef(1.0f, 1.0f + __expf(-pre[j]));
        m[j] = gte * lv[j];
    }

    float* dst = g_agg + (size_t)r * HID + sub;
    asm volatile("red.global.add.v4.f32 [%0], {%1,%2,%3,%4};"
                 :: "l"(dst), "f"(m[0]), "f"(m[1]), "f"(m[2]), "f"(m[3]) : "memory");
    asm volatile("red.global.add.v4.f32 [%0], {%1,%2,%3,%4};"
                 :: "l"(dst + 4), "f"(m[4]), "f"(m[5]), "f"(m[6]), "f"(m[7]) : "memory");
}

// ---------------------------------------------------------------------------
// 4. Node update: x = relu(agg + lin); agg = 0 (ready for next layer)
// ---------------------------------------------------------------------------
__global__ void __launch_bounds__(256) update_kernel() {
    int i = blockIdx.x * 256 + threadIdx.x;
    if (i < N_ATOMS * HID) {
        g_x[i] = fmaxf(g_agg[i] + g_lin[i], 0.0f);
        g_agg[i] = 0.0f;
    }
}

// ---------------------------------------------------------------------------
// 5. Mean pool (sum; mean applied in head)
// ---------------------------------------------------------------------------
__global__ void __launch_bounds__(256) pool_kernel() {
    int t = threadIdx.x;
    int col = t & 63;
    int grp = t >> 6;
    float acc = 0.0f;
    for (int node = blockIdx.x * 4 + grp; node < N_ATOMS; node += gridDim.x * 4)
        acc += g_x[node * HID + col];
    __shared__ float s[256];
    s[t] = acc;
    __syncthreads();
    if (grp == 0)
        atomicAdd(&g_pooled[col], s[col] + s[col + 64] + s[col + 128] + s[col + 192]);
}

// ---------------------------------------------------------------------------
// 6. MLP head: out = relu(pooled/N @ W1 + b1) @ W2 + b2
// ---------------------------------------------------------------------------
__global__ void head_kernel(const float* __restrict__ W1, const float* __restrict__ b1,
                            const float* __restrict__ W2, const float* __restrict__ b2,
                            float* __restrict__ out) {
    __shared__ float sp[64], sh[64];
    int t = threadIdx.x;
    if (t < 64) sp[t] = g_pooled[t] * (1.0f / (float)N_ATOMS);
    __syncthreads();
    if (t < 64) {
        float a = b1[t];
        #pragma unroll
        for (int k = 0; k < 64; k++) a += sp[k] * W1[k * 64 + t];
        sh[t] = fmaxf(a, 0.0f);
    }
    __syncthreads();
    if (t < 128) {
        float a = b2[t];
        #pragma unroll
        for (int k = 0; k < 64; k++) a += sh[k] * W2[k * 128 + t];
        out[t] = a;
    }
}

// ---------------------------------------------------------------------------
extern "C" void kernel_launch(void* const* d_in, const int* in_sizes, int n_in,
                              void* d_out, int out_size) {
    const int*   an  = (const int*)d_in[0];
    // d_in[1] positions, d_in[2] lattice: unused by reference
    const int*   ei  = (const int*)d_in[3];
    const float* emb = (const float*)d_in[4];
    const float* Wl  = (const float*)d_in[5];
    const float* bl  = (const float*)d_in[6];
    const float* Wg  = (const float*)d_in[7];
    const float* bg  = (const float*)d_in[8];
    const float* W1  = (const float*)d_in[9];
    const float* b1  = (const float*)d_in[10];
    const float* W2  = (const float*)d_in[11];
    const float* b2  = (const float*)d_in[12];
    float* out = (float*)d_out;

    cudaFuncSetAttribute(proj_kernel, cudaFuncAttributeMaxDynamicSharedMemorySize, PROJ_SMEM);

    const int nodeElemBlocks = (N_ATOMS * HID + 255) / 256;   // 25000
    const int projBlocks = (N_ATOMS + 63) / 64;               // 1563
    const int edgeBlocks = (N_EDGES * 8 + 255) / 256;         // 31250

    embed_kernel<<<nodeElemBlocks, 256>>>(an, emb);
    for (int l = 0; l < 3; l++) {
        proj_kernel<<<projBlocks, 256, PROJ_SMEM>>>(Wg + l * 128 * 64, bg + l * 64,
                                                    Wl + l * 64 * 64, bl + l * 64);
        edge_kernel<<<edgeBlocks, 256>>>(ei);
        update_kernel<<<nodeElemBlocks, 256>>>();
    }
    pool_kernel<<<512, 256>>>();
    head_kernel<<<1, 128>>>(W1, b1, W2, b2, out);
}

// round 2
// speedup vs baseline: 1.0763x; 1.0763x over previous
#include <cuda_runtime.h>
#include <cuda_fp16.h>
#include <cstdint>

// Problem constants
#define N_ATOMS 100000
#define N_EDGES 1000000
#define HID 64
#define OUTD 128

#define SCAN_T 512
#define SCAN_ITEMS (N_ATOMS + 1)
#define SCAN_NB ((SCAN_ITEMS + SCAN_T - 1) / SCAN_T)

// Scratch (device globals: allocation-free rule)
__device__ float  g_x[N_ATOMS * HID];      // node features
__device__ float  g_lin[N_ATOMS * HID];    // x @ W_lin + b_lin, fp32 (self term)
__device__ __half g_linh[N_ATOMS * HID];   // same, fp16 (edge messages)
__device__ __half g_gtop[N_ATOMS * HID];   // x @ Wg_top + b_gate (gate pre-act)
__device__ __half g_gbot[N_ATOMS * HID];   // x @ Wg_bot
__device__ float  g_pooled[HID];

// Edge CSR (built per launch by counting sort)
__device__ int g_cnt[SCAN_ITEMS];
__device__ int g_off[SCAN_ITEMS];
__device__ int g_cur[N_ATOMS];
__device__ int g_part[SCAN_NB];
__device__ int g_scol[N_EDGES];

// ---------------------------------------------------------------------------
// 1. Embedding lookup + zero counters/pooled
// ---------------------------------------------------------------------------
__global__ void __launch_bounds__(256) embed_kernel(const int* __restrict__ an,
                                                    const float* __restrict__ emb) {
    int i = blockIdx.x * 256 + threadIdx.x;
    if (i < N_ATOMS * HID) {
        int v = i >> 6;
        g_x[i] = emb[an[v] * HID + (i & 63)];
    }
    if (i < SCAN_ITEMS) g_cnt[i] = 0;
    if (i < HID) g_pooled[i] = 0.0f;
}

// ---------------------------------------------------------------------------
// 2. Counting sort of edges by row  (hist -> scan -> scatter)
// ---------------------------------------------------------------------------
__global__ void __launch_bounds__(256) hist_kernel(const int* __restrict__ ei) {
    int e = blockIdx.x * 256 + threadIdx.x;
    if (e < N_EDGES) atomicAdd(&g_cnt[ei[e]], 1);
}

__global__ void __launch_bounds__(SCAN_T) scan_a_kernel() {
    __shared__ int s[SCAN_T];
    int t = threadIdx.x;
    int i = blockIdx.x * SCAN_T + t;
    s[t] = (i < SCAN_ITEMS) ? g_cnt[i] : 0;
    __syncthreads();
    for (int d = SCAN_T / 2; d > 0; d >>= 1) {
        if (t < d) s[t] += s[t + d];
        __syncthreads();
    }
    if (t == 0) g_part[blockIdx.x] = s[0];
}

__global__ void scan_b_kernel() {
    if (threadIdx.x == 0) {
        int running = 0;
        for (int b = 0; b < SCAN_NB; b++) {
            int v = g_part[b];
            g_part[b] = running;
            running += v;
        }
    }
}

__global__ void __launch_bounds__(SCAN_T) scan_c_kernel() {
    __shared__ int s[SCAN_T];
    int t = threadIdx.x;
    int i = blockIdx.x * SCAN_T + t;
    int v = (i < SCAN_ITEMS) ? g_cnt[i] : 0;
    s[t] = v;
    __syncthreads();
    for (int d = 1; d < SCAN_T; d <<= 1) {
        int a = (t >= d) ? s[t - d] : 0;
        __syncthreads();
        s[t] += a;
        __syncthreads();
    }
    int off = g_part[blockIdx.x] + s[t] - v;  // exclusive
    if (i < SCAN_ITEMS) g_off[i] = off;
    if (i < N_ATOMS)    g_cur[i] = off;
}

__global__ void __launch_bounds__(256) scatter_kernel(const int* __restrict__ ei) {
    int e = blockIdx.x * 256 + threadIdx.x;
    if (e < N_EDGES) {
        int r = ei[e];
        int c = ei[N_EDGES + e];
        int p = atomicAdd(&g_cur[r], 1);
        g_scol[p] = c;
    }
}

// ---------------------------------------------------------------------------
// 3. Per-node projection: [64 nodes/block] x (64 -> 192) GEMM
//    cols 0..63   -> gtop (fp16, + b_gate folded in)
//    cols 64..127 -> gbot (fp16)
//    cols 128..191-> lin  (fp32 + fp16 copies, + b_lin)
// ---------------------------------------------------------------------------
#define XS_STRIDE 68
#define PROJ_SMEM ((64 * XS_STRIDE + 64 * 192) * 4)

__global__ void __launch_bounds__(256) proj_kernel(const float* __restrict__ Wg,
                                                   const float* __restrict__ bg,
                                                   const float* __restrict__ Wl,
                                                   const float* __restrict__ bl) {
    extern __shared__ float sm[];
    float* xsT = sm;                    // [64][XS_STRIDE]
    float* ws  = sm + 64 * XS_STRIDE;   // [64][192]

    const int tid = threadIdx.x;
    const int node0 = blockIdx.x * 64;

    for (int i = tid; i < 64 * 64; i += 256) {
        int k = i & 63, n = i >> 6;
        int node = node0 + n;
        xsT[k * XS_STRIDE + n] = (node < N_ATOMS) ? g_x[node * HID + k] : 0.0f;
    }
    for (int i = tid; i < 64 * 192; i += 256) {
        int k = i / 192, c = i - k * 192;
        float w;
        if (c < 64)        w = Wg[k * 64 + c];
        else if (c < 128)  w = Wg[(64 + k) * 64 + (c - 64)];
        else               w = Wl[k * 64 + (c - 128)];
        ws[i] = w;
    }
    __syncthreads();

    const int ng = tid & 7;
    const int cg = tid >> 3;
    const int nb = ng * 8;
    const int cb = cg * 6;

    float acc[8][6];
    #pragma unroll
    for (int n = 0; n < 8; n++)
        #pragma unroll
        for (int j = 0; j < 6; j++) acc[n][j] = 0.0f;

    #pragma unroll 8
    for (int k = 0; k < 64; k++) {
        const float* xr = &xsT[k * XS_STRIDE + nb];
        float4 a0 = *reinterpret_cast<const float4*>(xr);
        float4 a1 = *reinterpret_cast<const float4*>(xr + 4);
        float a[8] = {a0.x, a0.y, a0.z, a0.w, a1.x, a1.y, a1.z, a1.w};
        float b[6];
        #pragma unroll
        for (int j = 0; j < 6; j++) b[j] = ws[k * 192 + cb + j];
        #pragma unroll
        for (int n = 0; n < 8; n++)
            #pragma unroll
            for (int j = 0; j < 6; j++) acc[n][j] += a[n] * b[j];
    }

    for (int n = 0; n < 8; n++) {
        int node = node0 + nb + n;
        if (node >= N_ATOMS) break;
        #pragma unroll
        for (int j = 0; j < 6; j++) {
            int c = cb + j;
            if (c < 64) {
                g_gtop[node * HID + c] = __float2half(acc[n][j] + bg[c]);
            } else if (c < 128) {
                g_gbot[node * HID + (c - 64)] = __float2half(acc[n][j]);
            } else {
                float lv = acc[n][j] + bl[c - 128];
                g_lin[node * HID + (c - 128)] = lv;
                g_linh[node * HID + (c - 128)] = __float2half(lv);
            }
        }
    }
}

// ---------------------------------------------------------------------------
// 4. Gather-aggregate + fused node update.
//    One warp per node; lane handles 2 channels as half2.
//    x[v] = relu( lin[v] + sum_{c in N(v)} sigmoid(gtop[v]+gbot[c]) * linh[c] )
// ---------------------------------------------------------------------------
__global__ void __launch_bounds__(256) gather_kernel() {
    int w = (blockIdx.x * 256 + threadIdx.x) >> 5;
    int l = threadIdx.x & 31;
    if (w >= N_ATOMS) return;

    int beg = g_off[w];
    int end = g_off[w + 1];

    const __half2* gt2 = reinterpret_cast<const __half2*>(g_gtop);
    const __half2* gb2 = reinterpret_cast<const __half2*>(g_gbot);
    const __half2* lh2 = reinterpret_cast<const __half2*>(g_linh);

    float2 gtf = __half22float2(gt2[w * 32 + l]);
    float2 acc = *reinterpret_cast<const float2*>(g_lin + (size_t)w * HID + 2 * l);

    for (int base = beg; base < end; base += 32) {
        int myc = (base + l < end) ? g_scol[base + l] : 0;
        int m = min(32, end - base);
        #pragma unroll 4
        for (int j = 0; j < m; j++) {
            int cc = __shfl_sync(0xffffffffu, myc, j);
            float2 gbf = __half22float2(gb2[cc * 32 + l]);
            float2 lhf = __half22float2(lh2[cc * 32 + l]);
            float p0 = gtf.x + gbf.x;
            float p1 = gtf.y + gbf.y;
            float s0 = __fdividef(1.0f, 1.0f + __expf(-p0));
            float s1 = __fdividef(1.0f, 1.0f + __expf(-p1));
            acc.x += s0 * lhf.x;
            acc.y += s1 * lhf.y;
        }
    }

    float2 xo;
    xo.x = fmaxf(acc.x, 0.0f);
    xo.y = fmaxf(acc.y, 0.0f);
    *reinterpret_cast<float2*>(g_x + (size_t)w * HID + 2 * l) = xo;
}

// ---------------------------------------------------------------------------
// 5. Mean pool (sum; mean applied in head)
// ---------------------------------------------------------------------------
__global__ void __launch_bounds__(256) pool_kernel() {
    int t = threadIdx.x;
    int col = t & 63;
    int grp = t >> 6;
    float acc = 0.0f;
    for (int node = blockIdx.x * 4 + grp; node < N_ATOMS; node += gridDim.x * 4)
        acc += g_x[node * HID + col];
    __shared__ float s[256];
    s[t] = acc;
    __syncthreads();
    if (grp == 0)
        atomicAdd(&g_pooled[col], s[col] + s[col + 64] + s[col + 128] + s[col + 192]);
}

// ---------------------------------------------------------------------------
// 6. MLP head
// ---------------------------------------------------------------------------
__global__ void head_kernel(const float* __restrict__ W1, const float* __restrict__ b1,
                            const float* __restrict__ W2, const float* __restrict__ b2,
                            float* __restrict__ out) {
    __shared__ float sp[64], sh[64];
    int t = threadIdx.x;
    if (t < 64) sp[t] = g_pooled[t] * (1.0f / (float)N_ATOMS);
    __syncthreads();
    if (t < 64) {
        float a = b1[t];
        #pragma unroll
        for (int k = 0; k < 64; k++) a += sp[k] * W1[k * 64 + t];
        sh[t] = fmaxf(a, 0.0f);
    }
    __syncthreads();
    if (t < 128) {
        float a = b2[t];
        #pragma unroll
        for (int k = 0; k < 64; k++) a += sh[k] * W2[k * 128 + t];
        out[t] = a;
    }
}

// ---------------------------------------------------------------------------
extern "C" void kernel_launch(void* const* d_in, const int* in_sizes, int n_in,
                              void* d_out, int out_size) {
    const int*   an  = (const int*)d_in[0];
    const int*   ei  = (const int*)d_in[3];
    const float* emb = (const float*)d_in[4];
    const float* Wl  = (const float*)d_in[5];
    const float* bl  = (const float*)d_in[6];
    const float* Wg  = (const float*)d_in[7];
    const float* bg  = (const float*)d_in[8];
    const float* W1  = (const float*)d_in[9];
    const float* b1  = (const float*)d_in[10];
    const float* W2  = (const float*)d_in[11];
    const float* b2  = (const float*)d_in[12];
    float* out = (float*)d_out;

    cudaFuncSetAttribute(proj_kernel, cudaFuncAttributeMaxDynamicSharedMemorySize, PROJ_SMEM);

    const int nodeElemBlocks = (N_ATOMS * HID + 255) / 256;   // 25000
    const int projBlocks = (N_ATOMS + 63) / 64;               // 1563
    const int edgeBlocks = (N_EDGES + 255) / 256;             // 3907
    const int gatherBlocks = (N_ATOMS * 32 + 255) / 256;      // 12500

    embed_kernel<<<nodeElemBlocks, 256>>>(an, emb);
    hist_kernel<<<edgeBlocks, 256>>>(ei);
    scan_a_kernel<<<SCAN_NB, SCAN_T>>>();
    scan_b_kernel<<<1, 32>>>();
    scan_c_kernel<<<SCAN_NB, SCAN_T>>>();
    scatter_kernel<<<edgeBlocks, 256>>>(ei);

    for (int l = 0; l < 3; l++) {
        proj_kernel<<<projBlocks, 256, PROJ_SMEM>>>(Wg + l * 128 * 64, bg + l * 64,
                                                    Wl + l * 64 * 64, bl + l * 64);
        gather_kernel<<<gatherBlocks, 256>>>();
    }
    pool_kernel<<<512, 256>>>();
    head_kernel<<<1, 128>>>(W1, b1, W2, b2, out);
}